// round 3
// baseline (speedup 1.0000x reference)
#include <cuda_runtime.h>

// Problem constants (fixed by the dataset)
#define NN      100000      // nodes
#define DIN     256         // input feature dim
#define DOUT    32          // output feature dim
#define KC      32          // K-chunk for GEMM shared tile
#define RPB     256         // rows per GEMM block
#define GTHREADS 256

// Scratch for pre_sup = x @ W  [NN, DOUT] (12.8 MB, device global per rules)
__device__ float g_presup[(size_t)NN * DOUT];

typedef unsigned long long ull;

__device__ __forceinline__ void ffma2(ull& d, ull a, ull b) {
    // d = a * b + d   (packed 2x fp32, single HW FFMA2)
    asm volatile("fma.rn.f32x2 %0, %1, %2, %0;" : "+l"(d) : "l"(a), "l"(b));
}

__device__ __forceinline__ ull pack2(float x) {
    ull r;
    asm("mov.b64 %0, {%1, %1};" : "=l"(r) : "f"(x));
    return r;
}

__device__ __forceinline__ void unpack2(ull v, float& lo, float& hi) {
    asm("mov.b64 {%0, %1}, %2;" : "=f"(lo), "=f"(hi) : "l"(v));
}

// ---------------------------------------------------------------------------
// Kernel 1: GEMM  pre_sup[N, 32] = x[N, 256] @ W[256, 32]
// 256 threads/block covering 256 rows x 32 cols.
// Thread (tc = tid&3 -> cols tc*8..tc*8+7, tr = tid>>2 -> rows tr*4..tr*4+3)
// computes a 4-row x 8-col tile as 4x4 packed f32x2 accumulators via FFMA2.
// X tile stored K-MAJOR in smem: Xs[k][row], conflict-free for both the
// store phase (bank = lane) and the compute phase (8 distinct banks,
// 4-lane broadcast groups). Scalar/64-bit LDS only -> no alignment hazard.
// ---------------------------------------------------------------------------
__global__ __launch_bounds__(GTHREADS, 4) void gemm_kernel(const float* __restrict__ x,
                                                           const float* __restrict__ w) {
    __shared__ float Ws[KC * DOUT];      // 4 KB  (current K-chunk of W, row-major [k][32])
    __shared__ float Xs[KC * RPB];       // 32 KB (K-MAJOR: Xs[k*RPB + row])

    const int tid  = threadIdx.x;
    const int row0 = blockIdx.x * RPB;
    const int tc   = tid & 3;    // -> cols  tc*8 .. tc*8+7
    const int tr   = tid >> 2;   // -> rows  tr*4 .. tr*4+3

    ull acc[4][4];
#pragma unroll
    for (int r = 0; r < 4; r++)
#pragma unroll
        for (int c = 0; c < 4; c++) acc[r][c] = 0ULL;

    const int myrow   = row0 + tid;          // this thread's load row
    const bool rowok  = (myrow < NN);
    const float* xrow = x + (size_t)myrow * DIN;

    for (int kc = 0; kc < DIN; kc += KC) {
        __syncthreads();
        // Load W chunk [KC, 32] = 1024 floats = 256 float4 across 256 threads
        {
            const float4* wsrc = (const float4*)(w + (size_t)kc * DOUT);
            ((float4*)Ws)[tid] = wsrc[tid];
        }
        // Load X tile: thread tid owns global row (row0+tid); 8 float4 along k.
        // Store transposed into Xs[k][tid] -> 4 scalar STS each, bank = lane.
#pragma unroll
        for (int c4 = 0; c4 < KC / 4; c4++) {
            float4 v = make_float4(0.f, 0.f, 0.f, 0.f);
            if (rowok) v = *(const float4*)(xrow + kc + c4 * 4);
            Xs[(c4 * 4 + 0) * RPB + tid] = v.x;
            Xs[(c4 * 4 + 1) * RPB + tid] = v.y;
            Xs[(c4 * 4 + 2) * RPB + tid] = v.z;
            Xs[(c4 * 4 + 3) * RPB + tid] = v.w;
        }
        __syncthreads();

#pragma unroll 8
        for (int k = 0; k < KC; k++) {
            const float* wrow = Ws + k * DOUT + tc * 8;
            ull w0 = *(const ull*)(wrow + 0);   // cols (0,1) of this thread's 8
            ull w1 = *(const ull*)(wrow + 2);
            ull w2 = *(const ull*)(wrow + 4);
            ull w3 = *(const ull*)(wrow + 6);
            const float* xk = Xs + k * RPB + tr * 4;
#pragma unroll
            for (int r = 0; r < 4; r++) {
                ull xv = pack2(xk[r]);
                ffma2(acc[r][0], xv, w0);
                ffma2(acc[r][1], xv, w1);
                ffma2(acc[r][2], xv, w2);
                ffma2(acc[r][3], xv, w3);
            }
        }
    }

    // Epilogue: unpack and store two float4 per row
#pragma unroll
    for (int r = 0; r < 4; r++) {
        int grow = row0 + tr * 4 + r;
        if (grow < NN) {
            float4 o0, o1;
            unpack2(acc[r][0], o0.x, o0.y);
            unpack2(acc[r][1], o0.z, o0.w);
            unpack2(acc[r][2], o1.x, o1.y);
            unpack2(acc[r][3], o1.z, o1.w);
            float* dst = g_presup + (size_t)grow * DOUT + tc * 8;
            *(float4*)(dst + 0) = o0;
            *(float4*)(dst + 4) = o1;
        }
    }
}

// ---------------------------------------------------------------------------
// Kernel 2: Scatter SpMM  out[row[e]] += val[e] * pre_sup[col[e]]
// 8 threads per edge; each handles 4 columns via one float4 gather +
// one red.global.add.v4.f32 (sm_90+ vector reduction, no return).
// ---------------------------------------------------------------------------
__global__ __launch_bounds__(256) void scatter_kernel(const int*   __restrict__ arow,
                                                      const int*   __restrict__ acol,
                                                      const float* __restrict__ aval,
                                                      float*       __restrict__ out,
                                                      int n_edges) {
    long long g = (long long)blockIdx.x * blockDim.x + threadIdx.x;
    int e    = (int)(g >> 3);
    int part = (int)(g & 7);
    if (e >= n_edges) return;

    int   r = arow[e];
    int   c = acol[e];
    float v = aval[e];

    float4 p = *(const float4*)(g_presup + (size_t)c * DOUT + part * 4);
    float m0 = v * p.x, m1 = v * p.y, m2 = v * p.z, m3 = v * p.w;

    float* dst = out + (size_t)r * DOUT + part * 4;
    asm volatile("red.global.add.v4.f32 [%0], {%1, %2, %3, %4};"
                 :: "l"(dst), "f"(m0), "f"(m1), "f"(m2), "f"(m3)
                 : "memory");
}

// ---------------------------------------------------------------------------
// Kernel 3: in-place ReLU on out (after all reductions complete)
// ---------------------------------------------------------------------------
__global__ __launch_bounds__(256) void relu_kernel(float* __restrict__ out, int n4) {
    int i = blockIdx.x * blockDim.x + threadIdx.x;
    if (i < n4) {
        float4 v = ((float4*)out)[i];
        v.x = fmaxf(v.x, 0.f);
        v.y = fmaxf(v.y, 0.f);
        v.z = fmaxf(v.z, 0.f);
        v.w = fmaxf(v.w, 0.f);
        ((float4*)out)[i] = v;
    }
}

// ---------------------------------------------------------------------------
// kernel_launch: memset(out) -> gemm -> scatter -> relu   (all graph-capturable)
// Inputs (metadata order): x[N*256] f32, adj_row[E] i32, adj_col[E] i32,
//                          adj_val[E] f32, weight[256*32] f32. Output f32 [N*32].
// ---------------------------------------------------------------------------
extern "C" void kernel_launch(void* const* d_in, const int* in_sizes, int n_in,
                              void* d_out, int out_size) {
    const float* x    = (const float*)d_in[0];
    const int*   arow = (const int*)  d_in[1];
    const int*   acol = (const int*)  d_in[2];
    const float* aval = (const float*)d_in[3];
    const float* w    = (const float*)d_in[4];
    float*       out  = (float*)d_out;

    const int n_edges = in_sizes[1];

    cudaMemsetAsync(out, 0, (size_t)out_size * sizeof(float), 0);

    gemm_kernel<<<(NN + RPB - 1) / RPB, GTHREADS>>>(x, w);

    long long sthreads = (long long)n_edges * 8;
    int sblocks = (int)((sthreads + 255) / 256);
    scatter_kernel<<<sblocks, 256>>>(arow, acol, aval, out, n_edges);

    int n4 = out_size / 4;
    relu_kernel<<<(n4 + 255) / 256, 256>>>(out, n4);
}